// round 4
// baseline (speedup 1.0000x reference)
#include <cuda_runtime.h>

// Problem constants (shapes fixed by the dataset)
#define MAXN 100000
#define FEAT 64
#define NODES 32          // nodes per dense block
#define ASTRIDE 36        // padded node-stride in smem (avoids bank conflicts)

// Scratch (allocation-free rule: __device__ globals). Referenced ONLY from
// device code; host side does nothing but kernel launches.
__device__ float g_agg[MAXN * FEAT];
__device__ float g_cnt[MAXN];
__device__ float g_h1[MAXN * FEAT];

// ---------------------------------------------------------------------------
// Zero scratch. doCnt=1 also zeros the degree counter (layer 0 only).
// ---------------------------------------------------------------------------
__global__ void zero_kernel(int n, int doCnt)
{
    int i = blockIdx.x * blockDim.x + threadIdx.x;
    int stride = gridDim.x * blockDim.x;
    for (int j = i; j < n; j += stride) g_agg[j] = 0.0f;
    if (doCnt)
        for (int j = i; j < MAXN; j += stride) g_cnt[j] = 0.0f;
}

// ---------------------------------------------------------------------------
// Edge phase: one warp per edge. Gather h[src] row (256B coalesced; 25.6MB
// feature table is L2-resident), scatter-add into g_agg[dst] row (64
// consecutive fp32 RED ops -> sector-coalesced at LTS).
// NOTE: edge_index is INT32 (JAX default x64-disabled downgrades the
// requested int64 silently) — reading it as int64 was the R1-R3 crash.
// ---------------------------------------------------------------------------
__global__ void scatter_kernel(const float* __restrict__ x,
                               const int* __restrict__ src,
                               const int* __restrict__ dst,
                               int E, int hFromH1, int doCount)
{
    int warp = (int)((blockIdx.x * blockDim.x + threadIdx.x) >> 5);
    int lane = threadIdx.x & 31;
    if (warp >= E) return;
    const float* h = hFromH1 ? g_h1 : x;
    int s = src[warp];
    int t = dst[warp];
    float v0 = h[s * FEAT + lane];
    float v1 = h[s * FEAT + 32 + lane];
    atomicAdd(&g_agg[t * FEAT + lane], v0);
    atomicAdd(&g_agg[t * FEAT + 32 + lane], v1);
    if (doCount && lane == 0) atomicAdd(&g_cnt[t], 1.0f);
}

// ---------------------------------------------------------------------------
// Dense phase, fused per node n:
//   o = PReLU( (agg[n]/max(cnt,1))@wl^T + bl + h[n]@wr^T ) + x0[n]@ws^T + bs
// 256 threads = 64 output features x (32 nodes / 8 nodes-per-thread).
// Three GEMM phases share ONE 16KB weight tile + ONE 9.2KB activation tile
// (static smem 25.2KB, no attribute calls). Phases 0,1 share an accumulator;
// phase 2 (skip) uses a second.
// Weights staged transposed [k][d] (conflict-free); activations transposed
// [k][node] so 8 node-values load as two float4 broadcasts.
// ---------------------------------------------------------------------------
__global__ void __launch_bounds__(256) dense_kernel(
    const float* __restrict__ x,
    const float* __restrict__ w_l, const float* __restrict__ b_l,
    const float* __restrict__ w_r, const float* __restrict__ w_skip,
    const float* __restrict__ b_skip, const float* __restrict__ a,
    float* __restrict__ out, int N, int hFromH1, int outToH1)
{
    __shared__ __align__(16) float s_w[64 * 64];          // [k*64 + d]
    __shared__ __align__(16) float s_act[64 * ASTRIDE];   // [k*ASTRIDE + n]

    int tid  = threadIdx.x;
    int base = blockIdx.x * NODES;
    int d    = tid & 63;
    int n0   = (tid >> 6) * 8;              // 8 nodes per thread

    const float* h = hFromH1 ? g_h1 : x;

    float accA[8];   // agg@wl + h@wr
    float accS[8];   // x0@ws
#pragma unroll
    for (int j = 0; j < 8; j++) { accA[j] = 0.f; accS[j] = 0.f; }

#pragma unroll
    for (int phase = 0; phase < 3; phase++) {
        const float* w = (phase == 0) ? w_l : (phase == 1) ? w_r : w_skip;

        __syncthreads();   // protect previous phase's smem reads

        // stage weights transposed: w[d][k] -> s_w[k*64 + d]
        for (int i = tid; i < 64 * 64; i += 256) {
            int dd = i >> 6, kk = i & 63;
            s_w[kk * 64 + dd] = w[i];
        }
        // stage activations transposed: [k][n]
        for (int i = tid; i < NODES * 64; i += 256) {
            int n = i >> 6, k = i & 63;
            int gn = base + n;
            float v = 0.f;
            if (gn < N) {
                if (phase == 0)
                    v = g_agg[gn * FEAT + k] / fmaxf(g_cnt[gn], 1.0f);
                else if (phase == 1)
                    v = h[gn * FEAT + k];
                else
                    v = x[gn * FEAT + k];
            }
            s_act[k * ASTRIDE + n] = v;
        }
        __syncthreads();

        float* acc = (phase == 2) ? accS : accA;
#pragma unroll 4
        for (int k = 0; k < 64; k++) {
            float wv = s_w[k * 64 + d];
            float av[8];
            *(float4*)&av[0] = *(const float4*)&s_act[k * ASTRIDE + n0];
            *(float4*)&av[4] = *(const float4*)&s_act[k * ASTRIDE + n0 + 4];
#pragma unroll
            for (int j = 0; j < 8; j++)
                acc[j] = fmaf(av[j], wv, acc[j]);
        }
    }

    float bl = b_l[d];
    float bs = b_skip[d];
    float ap = a[d];
    float* dstp = outToH1 ? g_h1 : out;
#pragma unroll
    for (int j = 0; j < 8; j++) {
        int gn = base + n0 + j;
        if (gn < N) {
            float o = accA[j] + bl;
            o = (o >= 0.f) ? o : ap * o;
            dstp[gn * FEAT + d] = o + accS[j] + bs;
        }
    }
}

// ---------------------------------------------------------------------------
// Launch sequence: ONLY kernel launches (graph-capture safe).
// ---------------------------------------------------------------------------
extern "C" void kernel_launch(void* const* d_in, const int* in_sizes, int n_in,
                              void* d_out, int out_size)
{
    const float* x  = (const float*)d_in[0];
    const int*   ei = (const int*)d_in[1];     // int32! (JAX x64 disabled)
    int N = in_sizes[0] / FEAT;
    int E = in_sizes[1] / 2;
    const int* src = ei;
    const int* dst = ei + E;

    const float* w_l0    = (const float*)d_in[2];
    const float* b_l0    = (const float*)d_in[3];
    const float* w_r0    = (const float*)d_in[4];
    const float* w_skip0 = (const float*)d_in[5];
    const float* b_skip0 = (const float*)d_in[6];
    const float* a0      = (const float*)d_in[7];
    const float* w_l1    = (const float*)d_in[8];
    const float* b_l1    = (const float*)d_in[9];
    const float* w_r1    = (const float*)d_in[10];
    const float* w_skip1 = (const float*)d_in[11];
    const float* b_skip1 = (const float*)d_in[12];
    const float* a1      = (const float*)d_in[13];
    float* out = (float*)d_out;

    int sblocks = (int)(((long long)E * 32 + 255) / 256);
    int dblocks = (N + NODES - 1) / NODES;

    // layer 0: h = x, x0 = x -> g_h1
    zero_kernel<<<512, 256>>>(N * FEAT, 1);
    scatter_kernel<<<sblocks, 256>>>(x, src, dst, E, /*hFromH1=*/0, /*doCount=*/1);
    dense_kernel<<<dblocks, 256>>>(x, w_l0, b_l0, w_r0, w_skip0, b_skip0, a0,
                                   out, N, /*hFromH1=*/0, /*outToH1=*/1);

    // layer 1: h = g_h1, x0 = x -> out
    zero_kernel<<<512, 256>>>(N * FEAT, 0);
    scatter_kernel<<<sblocks, 256>>>(x, src, dst, E, /*hFromH1=*/1, /*doCount=*/0);
    dense_kernel<<<dblocks, 256>>>(x, w_l1, b_l1, w_r1, w_skip1, b_skip1, a1,
                                   out, N, /*hFromH1=*/1, /*outToH1=*/0);
}

// round 5
// speedup vs baseline: 1.3733x; 1.3733x over previous
#include <cuda_runtime.h>

// Problem constants (shapes fixed by the dataset)
#define MAXN 100000
#define MAXE 1600000
#define FEAT 64
#define NODES 32          // nodes per dense block
#define ASTRIDE 36        // padded node-stride in smem
#define SCAN_CHUNK 2048   // items per scan block (256 thr x 8)
#define MAXBLK 64         // max scan blocks (ceil(1e5/2048)=49)

// Scratch (__device__ globals; allocation-free rule)
__device__ float g_h1[MAXN * FEAT];
__device__ float g_agg[MAXN * FEAT];
__device__ int   g_cnt[MAXN];       // in-degree
__device__ int   g_off[MAXN];       // CSR row offsets (exclusive scan of cnt)
__device__ int   g_cur[MAXN];       // fill cursors
__device__ int   g_csr_src[MAXE];   // src ids bucketed by dst
__device__ int   g_bsum[MAXBLK];

// ---------------------------------------------------------------------------
// CSR build step 1: zero degree counters.
// ---------------------------------------------------------------------------
__global__ void zero_cnt_kernel(int n)
{
    int i = blockIdx.x * blockDim.x + threadIdx.x;
    if (i < n) g_cnt[i] = 0;
}

// step 2: histogram of dst (int atomics, spread addresses -> fast)
__global__ void hist_kernel(const int* __restrict__ dst, int E)
{
    int e = blockIdx.x * blockDim.x + threadIdx.x;
    if (e < E) atomicAdd(&g_cnt[dst[e]], 1);
}

// step 3a: per-chunk exclusive scan (256 threads x 8 items = 2048/block)
__global__ void scan1_kernel(int n)
{
    __shared__ int s_sum[256];
    int t = threadIdx.x;
    int base = blockIdx.x * SCAN_CHUNK + t * 8;
    int v[8], tot = 0;
#pragma unroll
    for (int j = 0; j < 8; j++) {
        int idx = base + j;
        v[j] = (idx < n) ? g_cnt[idx] : 0;
        tot += v[j];
    }
    s_sum[t] = tot;
    __syncthreads();
    // Hillis-Steele inclusive scan over thread totals
    for (int off = 1; off < 256; off <<= 1) {
        int x = (t >= off) ? s_sum[t - off] : 0;
        __syncthreads();
        s_sum[t] += x;
        __syncthreads();
    }
    if (t == 255) g_bsum[blockIdx.x] = s_sum[255];
    int run = s_sum[t] - tot;   // exclusive prefix for this thread
#pragma unroll
    for (int j = 0; j < 8; j++) {
        int idx = base + j;
        if (idx < n) g_off[idx] = run;
        run += v[j];
    }
}

// step 3b: exclusive scan of block sums (tiny)
__global__ void scan2_kernel(int nb)
{
    if (threadIdx.x == 0 && blockIdx.x == 0) {
        int run = 0;
        for (int i = 0; i < nb; i++) { int v = g_bsum[i]; g_bsum[i] = run; run += v; }
    }
}

// step 3c: add block offsets; init fill cursors
__global__ void scan3_kernel(int n)
{
    int i = blockIdx.x * blockDim.x + threadIdx.x;
    if (i < n) {
        int o = g_off[i] + g_bsum[i / SCAN_CHUNK];
        g_off[i] = o;
        g_cur[i] = o;
    }
}

// step 4: bucket edges by dst (order within bucket irrelevant for a sum)
__global__ void fill_kernel(const int* __restrict__ src,
                            const int* __restrict__ dst, int E)
{
    int e = blockIdx.x * blockDim.x + threadIdx.x;
    if (e < E) {
        int p = atomicAdd(&g_cur[dst[e]], 1);
        g_csr_src[p] = src[e];
    }
}

// ---------------------------------------------------------------------------
// Aggregate: one warp per node. Lanes sweep the neighbor list (index reads are
// warp-broadcast sectors), accumulate 2 regs/lane (64 feats), write mean once.
// No atomics; gathers hit the L2-resident feature table.
// ---------------------------------------------------------------------------
__global__ void agg_kernel(const float* __restrict__ x, int N, int hFromH1)
{
    int node = (int)((blockIdx.x * blockDim.x + threadIdx.x) >> 5);
    int lane = threadIdx.x & 31;
    if (node >= N) return;
    const float* h = hFromH1 ? g_h1 : x;

    int start = g_off[node];
    int deg   = g_cnt[node];

    float a0 = 0.f, a1 = 0.f;
    int i = 0;
    for (; i + 4 <= deg; i += 4) {
        int s0 = g_csr_src[start + i];
        int s1 = g_csr_src[start + i + 1];
        int s2 = g_csr_src[start + i + 2];
        int s3 = g_csr_src[start + i + 3];
        a0 += h[s0 * FEAT + lane] + h[s1 * FEAT + lane]
            + h[s2 * FEAT + lane] + h[s3 * FEAT + lane];
        a1 += h[s0 * FEAT + 32 + lane] + h[s1 * FEAT + 32 + lane]
            + h[s2 * FEAT + 32 + lane] + h[s3 * FEAT + 32 + lane];
    }
    for (; i < deg; i++) {
        int s = g_csr_src[start + i];
        a0 += h[s * FEAT + lane];
        a1 += h[s * FEAT + 32 + lane];
    }
    float inv = 1.f / fmaxf((float)deg, 1.f);
    g_agg[node * FEAT + lane]      = a0 * inv;
    g_agg[node * FEAT + 32 + lane] = a1 * inv;
}

// ---------------------------------------------------------------------------
// Dense phase, fused per node n:
//   o = PReLU( agg[n]@wl^T + bl + h[n]@wr^T ) + x0[n]@ws^T + bs
// (agg already divided by degree). 256 threads = 64 feats x 4 groups of 8
// nodes. Three GEMM phases reuse one weight tile + one activation tile
// (static smem 25.2KB). Weights [k][d]; activations [k][node] -> float4 loads.
// ---------------------------------------------------------------------------
__global__ void __launch_bounds__(256) dense_kernel(
    const float* __restrict__ x,
    const float* __restrict__ w_l, const float* __restrict__ b_l,
    const float* __restrict__ w_r, const float* __restrict__ w_skip,
    const float* __restrict__ b_skip, const float* __restrict__ a,
    float* __restrict__ out, int N, int hFromH1, int outToH1)
{
    __shared__ __align__(16) float s_w[64 * 64];          // [k*64 + d]
    __shared__ __align__(16) float s_act[64 * ASTRIDE];   // [k*ASTRIDE + n]

    int tid  = threadIdx.x;
    int base = blockIdx.x * NODES;
    int d    = tid & 63;
    int n0   = (tid >> 6) * 8;

    const float* h = hFromH1 ? g_h1 : x;

    float accA[8];   // agg@wl + h@wr
    float accS[8];   // x0@ws
#pragma unroll
    for (int j = 0; j < 8; j++) { accA[j] = 0.f; accS[j] = 0.f; }

#pragma unroll
    for (int phase = 0; phase < 3; phase++) {
        const float* w = (phase == 0) ? w_l : (phase == 1) ? w_r : w_skip;

        __syncthreads();

        for (int i = tid; i < 64 * 64; i += 256) {
            int dd = i >> 6, kk = i & 63;
            s_w[kk * 64 + dd] = w[i];
        }
        for (int i = tid; i < NODES * 64; i += 256) {
            int n = i >> 6, k = i & 63;
            int gn = base + n;
            float v = 0.f;
            if (gn < N) {
                if (phase == 0)      v = g_agg[gn * FEAT + k];
                else if (phase == 1) v = h[gn * FEAT + k];
                else                 v = x[gn * FEAT + k];
            }
            s_act[k * ASTRIDE + n] = v;
        }
        __syncthreads();

        float* acc = (phase == 2) ? accS : accA;
#pragma unroll 4
        for (int k = 0; k < 64; k++) {
            float wv = s_w[k * 64 + d];
            float av[8];
            *(float4*)&av[0] = *(const float4*)&s_act[k * ASTRIDE + n0];
            *(float4*)&av[4] = *(const float4*)&s_act[k * ASTRIDE + n0 + 4];
#pragma unroll
            for (int j = 0; j < 8; j++)
                acc[j] = fmaf(av[j], wv, acc[j]);
        }
    }

    float bl = b_l[d];
    float bs = b_skip[d];
    float ap = a[d];
    float* dstp = outToH1 ? g_h1 : out;
#pragma unroll
    for (int j = 0; j < 8; j++) {
        int gn = base + n0 + j;
        if (gn < N) {
            float o = accA[j] + bl;
            o = (o >= 0.f) ? o : ap * o;
            dstp[gn * FEAT + d] = o + accS[j] + bs;
        }
    }
}

// ---------------------------------------------------------------------------
// Launch sequence: only kernel launches (graph-capture safe).
// ---------------------------------------------------------------------------
extern "C" void kernel_launch(void* const* d_in, const int* in_sizes, int n_in,
                              void* d_out, int out_size)
{
    const float* x  = (const float*)d_in[0];
    const int*   ei = (const int*)d_in[1];   // int32 (JAX x64 disabled)
    int N = in_sizes[0] / FEAT;
    int E = in_sizes[1] / 2;
    const int* src = ei;
    const int* dst = ei + E;

    const float* w_l0    = (const float*)d_in[2];
    const float* b_l0    = (const float*)d_in[3];
    const float* w_r0    = (const float*)d_in[4];
    const float* w_skip0 = (const float*)d_in[5];
    const float* b_skip0 = (const float*)d_in[6];
    const float* a0      = (const float*)d_in[7];
    const float* w_l1    = (const float*)d_in[8];
    const float* b_l1    = (const float*)d_in[9];
    const float* w_r1    = (const float*)d_in[10];
    const float* w_skip1 = (const float*)d_in[11];
    const float* b_skip1 = (const float*)d_in[12];
    const float* a1      = (const float*)d_in[13];
    float* out = (float*)d_out;

    int eblocks  = (E + 255) / 256;
    int nblocks  = (N + 255) / 256;
    int sblocks  = (N + SCAN_CHUNK - 1) / SCAN_CHUNK;
    int ablocks  = (N * 32 + 255) / 256;
    int dblocks  = (N + NODES - 1) / NODES;

    // ---- CSR build (once; same graph both layers) ----
    zero_cnt_kernel<<<nblocks, 256>>>(N);
    hist_kernel<<<eblocks, 256>>>(dst, E);
    scan1_kernel<<<sblocks, 256>>>(N);
    scan2_kernel<<<1, 32>>>(sblocks);
    scan3_kernel<<<nblocks, 256>>>(N);
    fill_kernel<<<eblocks, 256>>>(src, dst, E);

    // ---- layer 0: h = x, x0 = x -> g_h1 ----
    agg_kernel<<<ablocks, 256>>>(x, N, /*hFromH1=*/0);
    dense_kernel<<<dblocks, 256>>>(x, w_l0, b_l0, w_r0, w_skip0, b_skip0, a0,
                                   out, N, /*hFromH1=*/0, /*outToH1=*/1);

    // ---- layer 1: h = g_h1, x0 = x -> out ----
    agg_kernel<<<ablocks, 256>>>(x, N, /*hFromH1=*/1);
    dense_kernel<<<dblocks, 256>>>(x, w_l1, b_l1, w_r1, w_skip1, b_skip1, a1,
                                   out, N, /*hFromH1=*/1, /*outToH1=*/0);
}

// round 6
// speedup vs baseline: 1.5996x; 1.1648x over previous
#include <cuda_runtime.h>

// Problem constants (shapes fixed by the dataset)
#define MAXN 100000
#define MAXE 1600000
#define FEAT 64
#define DNODES 64         // nodes per dense block
#define AST 68            // padded node-stride in act smem
#define SCAN_CHUNK 2048   // items per csr_build block (256 thr x 8)
#define MAXBLK 64

// Scratch (__device__ globals; allocation-free rule). Zero-initialized at
// module load; cleanup_kernel restores the invariant at end of every call.
__device__ float g_h1[MAXN * FEAT];
__device__ float g_agg[MAXN * FEAT];
__device__ int   g_cnt[MAXN];       // in-degree (must be 0 on call entry)
__device__ int   g_off[MAXN];       // CSR row offsets
__device__ int   g_cur[MAXN];       // fill cursors
__device__ int   g_csr_src[MAXE];   // src ids bucketed by dst
__device__ int   g_bsum[MAXBLK];
__device__ int   g_bar;             // grid-barrier counter (0 on call entry)

// ---------------------------------------------------------------------------
// Edge histogram: g_cnt[dst]++ (spread int atomics).
// ---------------------------------------------------------------------------
__global__ void hist_kernel(const int* __restrict__ dst, int E)
{
    int e = blockIdx.x * blockDim.x + threadIdx.x;
    if (e < E) atomicAdd(&g_cnt[dst[e]], 1);
}

// Software grid barrier: all 49 blocks are co-resident (148 SMs), so spinning
// is safe and deterministic.
__device__ __forceinline__ void grid_bar(int target)
{
    __syncthreads();
    if (threadIdx.x == 0) {
        __threadfence();
        atomicAdd(&g_bar, 1);
        while (atomicAdd(&g_bar, 0) < target) { }
    }
    __syncthreads();
}

// ---------------------------------------------------------------------------
// Fused CSR build (49 blocks): local exclusive scan -> barrier ->
// global offsets (sum 49 block-sums) -> barrier -> bucket edges by dst.
// ---------------------------------------------------------------------------
__global__ void csr_build_kernel(const int* __restrict__ src,
                                 const int* __restrict__ dst,
                                 int N, int E, int nb)
{
    __shared__ int s_sum[256];
    int t = threadIdx.x;
    int base = blockIdx.x * SCAN_CHUNK + t * 8;

    // local scan over 8 items/thread
    int v[8], tot = 0;
#pragma unroll
    for (int j = 0; j < 8; j++) {
        int idx = base + j;
        v[j] = (idx < N) ? g_cnt[idx] : 0;
        tot += v[j];
    }
    s_sum[t] = tot;
    __syncthreads();
    for (int off = 1; off < 256; off <<= 1) {
        int xv = (t >= off) ? s_sum[t - off] : 0;
        __syncthreads();
        s_sum[t] += xv;
        __syncthreads();
    }
    if (t == 255) g_bsum[blockIdx.x] = s_sum[255];
    int run = s_sum[t] - tot;   // exclusive prefix within block

    grid_bar(nb);               // all block sums visible

    // block prefix = sum of earlier block sums (nb<=49, trivial)
    int bpre = 0;
    for (int b = 0; b < (int)blockIdx.x; b++) bpre += g_bsum[b];
    run += bpre;
#pragma unroll
    for (int j = 0; j < 8; j++) {
        int idx = base + j;
        if (idx < N) { g_off[idx] = run; g_cur[idx] = run; }
        run += v[j];
    }

    grid_bar(2 * nb);           // all offsets/cursors visible

    // fill: bucket edges by dst (order within bucket irrelevant for a sum)
    int stride = gridDim.x * blockDim.x;
    for (int e = blockIdx.x * blockDim.x + t; e < E; e += stride) {
        int p = atomicAdd(&g_cur[dst[e]], 1);
        g_csr_src[p] = src[e];
    }
}

// ---------------------------------------------------------------------------
// Aggregate: one warp per node; lanes sweep the neighbor list, write mean.
// Gathers hit the L2-resident feature table; no fp atomics.
// ---------------------------------------------------------------------------
__global__ void agg_kernel(const float* __restrict__ x, int N, int hFromH1)
{
    int node = (int)((blockIdx.x * blockDim.x + threadIdx.x) >> 5);
    int lane = threadIdx.x & 31;
    if (node >= N) return;
    const float* h = hFromH1 ? g_h1 : x;

    int start = g_off[node];
    int deg   = g_cnt[node];

    float a0 = 0.f, a1 = 0.f;
    int i = 0;
    for (; i + 4 <= deg; i += 4) {
        int s0 = g_csr_src[start + i];
        int s1 = g_csr_src[start + i + 1];
        int s2 = g_csr_src[start + i + 2];
        int s3 = g_csr_src[start + i + 3];
        a0 += h[s0 * FEAT + lane] + h[s1 * FEAT + lane]
            + h[s2 * FEAT + lane] + h[s3 * FEAT + lane];
        a1 += h[s0 * FEAT + 32 + lane] + h[s1 * FEAT + 32 + lane]
            + h[s2 * FEAT + 32 + lane] + h[s3 * FEAT + 32 + lane];
    }
    for (; i < deg; i++) {
        int s = g_csr_src[start + i];
        a0 += h[s * FEAT + lane];
        a1 += h[s * FEAT + 32 + lane];
    }
    float inv = 1.f / fmaxf((float)deg, 1.f);
    g_agg[node * FEAT + lane]      = a0 * inv;
    g_agg[node * FEAT + 32 + lane] = a1 * inv;
}

// ---------------------------------------------------------------------------
// Dense phase, fused per node n:
//   o = PReLU( agg[n]@wl^T + bl + h[n]@wr^T ) + x0[n]@ws^T + bs
// 64 nodes/block, 256 threads = 64 feats x 4 groups of 16 nodes.
// All 3 weight tiles staged once (48KB, [k][d]); one act tile (64x68, [k][n])
// restaged per phase — except phase 2 reuses phase 1's tile when h==x (layer 0).
// Dynamic smem 65.4KB -> 3 blocks/SM. FMA-bound by design (LDS 40 vs FMA 64
// cyc per k-phase per SM).
// ---------------------------------------------------------------------------
__global__ void __launch_bounds__(256) dense_kernel(
    const float* __restrict__ x,
    const float* __restrict__ w_l, const float* __restrict__ b_l,
    const float* __restrict__ w_r, const float* __restrict__ w_skip,
    const float* __restrict__ b_skip, const float* __restrict__ a,
    float* __restrict__ out, int N, int hFromH1, int outToH1)
{
    extern __shared__ __align__(16) float sm[];
    float* s_w   = sm;                 // 3 x [64][64] : wl | wr | ws
    float* s_act = sm + 3 * 64 * 64;   // [64][AST]

    int tid  = threadIdx.x;
    int base = blockIdx.x * DNODES;
    int d    = tid & 63;
    int n0   = (tid >> 6) * 16;        // 16 nodes per thread

    const float* h = hFromH1 ? g_h1 : x;
    const bool hIsX = (hFromH1 == 0);

    // stage all weights transposed: w[dd][kk] -> s_w[kk*64+dd]
    for (int i = tid; i < 64 * 64; i += 256) {
        int dd = i >> 6, kk = i & 63;
        s_w[kk * 64 + dd]               = w_l[i];
        s_w[4096 + kk * 64 + dd]        = w_r[i];
        s_w[8192 + kk * 64 + dd]        = w_skip[i];
    }

    float accA[16], accS[16];
#pragma unroll
    for (int j = 0; j < 16; j++) { accA[j] = 0.f; accS[j] = 0.f; }

#pragma unroll
    for (int phase = 0; phase < 3; phase++) {
        bool reuse = (phase == 2) && hIsX;   // layer 0: x tile already staged
        if (!reuse) {
            __syncthreads();   // protect prior phase's reads (and weight stage)
            const float* srcm = (phase == 0) ? g_agg : (phase == 1) ? h : x;
            for (int i = tid; i < DNODES * 64; i += 256) {
                int n = i >> 6, k = i & 63;
                int gn = base + n;
                s_act[k * AST + n] = (gn < N) ? srcm[gn * FEAT + k] : 0.f;
            }
            __syncthreads();
        }

        const float* w = s_w + phase * 4096;
        float* acc = (phase == 2) ? accS : accA;
#pragma unroll 4
        for (int k = 0; k < 64; k++) {
            float wv = w[k * 64 + d];
            float av[16];
            *(float4*)&av[0]  = *(const float4*)&s_act[k * AST + n0];
            *(float4*)&av[4]  = *(const float4*)&s_act[k * AST + n0 + 4];
            *(float4*)&av[8]  = *(const float4*)&s_act[k * AST + n0 + 8];
            *(float4*)&av[12] = *(const float4*)&s_act[k * AST + n0 + 12];
#pragma unroll
            for (int j = 0; j < 16; j++)
                acc[j] = fmaf(av[j], wv, acc[j]);
        }
    }

    float bl = b_l[d];
    float bs = b_skip[d];
    float ap = a[d];
    float* dstp = outToH1 ? g_h1 : out;
#pragma unroll
    for (int j = 0; j < 16; j++) {
        int gn = base + n0 + j;
        if (gn < N) {
            float o = accA[j] + bl;
            o = (o >= 0.f) ? o : ap * o;
            dstp[gn * FEAT + d] = o + accS[j] + bs;
        }
    }
}

// ---------------------------------------------------------------------------
// Cleanup: restore call-entry invariants (g_cnt=0, g_bar=0) for next replay.
// ---------------------------------------------------------------------------
__global__ void cleanup_kernel(int N)
{
    int i = blockIdx.x * blockDim.x + threadIdx.x;
    if (i < N) g_cnt[i] = 0;
    if (i == 0) g_bar = 0;
}

// ---------------------------------------------------------------------------
// Launch sequence (dense at launch index 3 -> ncu's profiled slot).
// ---------------------------------------------------------------------------
extern "C" void kernel_launch(void* const* d_in, const int* in_sizes, int n_in,
                              void* d_out, int out_size)
{
    const float* x  = (const float*)d_in[0];
    const int*   ei = (const int*)d_in[1];   // int32 (JAX x64 disabled)
    int N = in_sizes[0] / FEAT;
    int E = in_sizes[1] / 2;
    const int* src = ei;
    const int* dst = ei + E;

    const float* w_l0    = (const float*)d_in[2];
    const float* b_l0    = (const float*)d_in[3];
    const float* w_r0    = (const float*)d_in[4];
    const float* w_skip0 = (const float*)d_in[5];
    const float* b_skip0 = (const float*)d_in[6];
    const float* a0      = (const float*)d_in[7];
    const float* w_l1    = (const float*)d_in[8];
    const float* b_l1    = (const float*)d_in[9];
    const float* w_r1    = (const float*)d_in[10];
    const float* w_skip1 = (const float*)d_in[11];
    const float* b_skip1 = (const float*)d_in[12];
    const float* a1      = (const float*)d_in[13];
    float* out = (float*)d_out;

    size_t dsmem = (size_t)(3 * 64 * 64 + 64 * AST) * sizeof(float); // 66560 B
    cudaFuncSetAttribute(dense_kernel, cudaFuncAttributeMaxDynamicSharedMemorySize,
                         (int)dsmem);

    int eblocks = (E + 255) / 256;
    int nb      = (N + SCAN_CHUNK - 1) / SCAN_CHUNK;   // 49
    int ablocks = (N * 32 + 255) / 256;
    int dblocks = (N + DNODES - 1) / DNODES;
    int nblocks = (N + 255) / 256;

    // CSR build (g_cnt, g_bar are 0 on entry: module init / cleanup_kernel)
    hist_kernel<<<eblocks, 256>>>(dst, E);                         // 0
    csr_build_kernel<<<nb, 256>>>(src, dst, N, E, nb);             // 1

    // layer 0: h = x -> g_h1
    agg_kernel<<<ablocks, 256>>>(x, N, 0);                         // 2
    dense_kernel<<<dblocks, 256, dsmem>>>(x, w_l0, b_l0, w_r0,     // 3 <- profiled
                                          w_skip0, b_skip0, a0,
                                          out, N, 0, 1);

    // layer 1: h = g_h1 -> out
    agg_kernel<<<ablocks, 256>>>(x, N, 1);                         // 4
    dense_kernel<<<dblocks, 256, dsmem>>>(x, w_l1, b_l1, w_r1,     // 5
                                          w_skip1, b_skip1, a1,
                                          out, N, 1, 0);

    cleanup_kernel<<<nblocks, 256>>>(N);                           // 6
}

// round 7
// speedup vs baseline: 2.4653x; 1.5412x over previous
#include <cuda_runtime.h>

// Problem constants (shapes fixed by the dataset)
#define MAXN 100000
#define MAXE 1600000
#define FEAT 64
#define DN 128            // nodes per dense block
#define AP 130            // act smem stride (even: 8B-aligned LDS.64, 2-way max)
#define WP 66             // weight smem stride (even, 2-way max)
#define SCAN_CHUNK 2048
#define MAXBLK 64

typedef unsigned long long ull;

// Scratch (__device__ globals; allocation-free rule). Zero-init at load;
// cleanup_kernel restores call-entry invariants every call.
__device__ float g_h1[MAXN * FEAT];
__device__ float g_agg[MAXN * FEAT];
__device__ int   g_cnt[MAXN];
__device__ int   g_off[MAXN];
__device__ int   g_cur[MAXN];
__device__ int   g_csr_src[MAXE];
__device__ int   g_bsum[MAXBLK];
__device__ int   g_bar;

// ---- packed f32x2 helpers (Blackwell PTX) ----------------------------------
__device__ __forceinline__ void fma2(ull& acc, ull av, ull wv)
{
    asm("fma.rn.f32x2 %0, %1, %2, %0;" : "+l"(acc) : "l"(av), "l"(wv));
}
__device__ __forceinline__ ull dup2(float w)
{
    ull r; asm("mov.b64 %0, {%1, %1};" : "=l"(r) : "f"(w)); return r;
}
__device__ __forceinline__ void unpk(float& lo, float& hi, ull v)
{
    asm("mov.b64 {%0, %1}, %2;" : "=f"(lo), "=f"(hi) : "l"(v));
}

// ---------------------------------------------------------------------------
// Edge histogram: g_cnt[dst]++ (spread int atomics).
// ---------------------------------------------------------------------------
__global__ void hist_kernel(const int* __restrict__ dst, int E)
{
    int e = blockIdx.x * blockDim.x + threadIdx.x;
    if (e < E) atomicAdd(&g_cnt[dst[e]], 1);
}

// Software grid barrier (all 49 blocks co-resident on 148 SMs).
__device__ __forceinline__ void grid_bar(int target)
{
    __syncthreads();
    if (threadIdx.x == 0) {
        __threadfence();
        atomicAdd(&g_bar, 1);
        while (atomicAdd(&g_bar, 0) < target) { }
    }
    __syncthreads();
}

// ---------------------------------------------------------------------------
// Fused CSR build: local scan -> bar -> global offsets -> bar -> edge fill.
// ---------------------------------------------------------------------------
__global__ void csr_build_kernel(const int* __restrict__ src,
                                 const int* __restrict__ dst,
                                 int N, int E, int nb)
{
    __shared__ int s_sum[256];
    int t = threadIdx.x;
    int base = blockIdx.x * SCAN_CHUNK + t * 8;

    int v[8], tot = 0;
#pragma unroll
    for (int j = 0; j < 8; j++) {
        int idx = base + j;
        v[j] = (idx < N) ? g_cnt[idx] : 0;
        tot += v[j];
    }
    s_sum[t] = tot;
    __syncthreads();
    for (int off = 1; off < 256; off <<= 1) {
        int xv = (t >= off) ? s_sum[t - off] : 0;
        __syncthreads();
        s_sum[t] += xv;
        __syncthreads();
    }
    if (t == 255) g_bsum[blockIdx.x] = s_sum[255];
    int run = s_sum[t] - tot;

    grid_bar(nb);

    int bpre = 0;
    for (int b = 0; b < (int)blockIdx.x; b++) bpre += g_bsum[b];
    run += bpre;
#pragma unroll
    for (int j = 0; j < 8; j++) {
        int idx = base + j;
        if (idx < N) { g_off[idx] = run; g_cur[idx] = run; }
        run += v[j];
    }

    grid_bar(2 * nb);

    int stride = gridDim.x * blockDim.x;
    for (int e = blockIdx.x * blockDim.x + t; e < E; e += stride) {
        int p = atomicAdd(&g_cur[dst[e]], 1);
        g_csr_src[p] = src[e];
    }
}

// ---------------------------------------------------------------------------
// Aggregate: one warp per node; lane covers feats (2l, 2l+1) as float2 ->
// one LDG.64 per source row. Unroll 4 for MLP. Writes mean once.
// ---------------------------------------------------------------------------
__global__ void agg_kernel(const float* __restrict__ x, int N, int hFromH1)
{
    int node = (int)((blockIdx.x * blockDim.x + threadIdx.x) >> 5);
    int lane = threadIdx.x & 31;
    if (node >= N) return;
    const float2* h2 = (const float2*)(hFromH1 ? g_h1 : x);

    int start = g_off[node];
    int deg   = g_cnt[node];

    float ax = 0.f, ay = 0.f;
    int i = 0;
    for (; i + 4 <= deg; i += 4) {
        int s0 = g_csr_src[start + i];
        int s1 = g_csr_src[start + i + 1];
        int s2 = g_csr_src[start + i + 2];
        int s3 = g_csr_src[start + i + 3];
        float2 v0 = h2[s0 * 32 + lane];
        float2 v1 = h2[s1 * 32 + lane];
        float2 v2 = h2[s2 * 32 + lane];
        float2 v3 = h2[s3 * 32 + lane];
        ax += (v0.x + v1.x) + (v2.x + v3.x);
        ay += (v0.y + v1.y) + (v2.y + v3.y);
    }
    for (; i < deg; i++) {
        int s = g_csr_src[start + i];
        float2 v = h2[s * 32 + lane];
        ax += v.x; ay += v.y;
    }
    float inv = 1.f / fmaxf((float)deg, 1.f);
    float2 r; r.x = ax * inv; r.y = ay * inv;
    ((float2*)g_agg)[node * 32 + lane] = r;
}

// ---------------------------------------------------------------------------
// Dense phase, fused per node n:
//   o = PReLU( agg[n]@wl^T + bl + h[n]@wr^T ) + x0[n]@ws^T + bs
// Block: 256 threads tile 64 feats x 128 nodes; thread tile 4d x 8n (4 f32x2
// node-pairs). Per k: 2 LDS.64 weights + 4 LDS.64 acts + 4 dup movs ->
// 16 fma.rn.f32x2 (32 MACs). Per-phase staging of one weight tile [k][WP]
// and one act tile [k][AP]; layer 0 reuses the x act-tile for the skip phase.
// ---------------------------------------------------------------------------
__global__ void __launch_bounds__(256, 2) dense_kernel(
    const float* __restrict__ x,
    const float* __restrict__ w_l, const float* __restrict__ b_l,
    const float* __restrict__ w_r, const float* __restrict__ w_skip,
    const float* __restrict__ b_skip, const float* __restrict__ a,
    float* __restrict__ out, int N, int hFromH1, int outToH1)
{
    extern __shared__ __align__(16) float sm[];
    float* s_w   = sm;            // [64][WP]
    float* s_act = sm + 64 * WP;  // [64][AP]

    int tid  = threadIdx.x;
    int base = blockIdx.x * DN;
    int d0   = (tid & 15) * 4;    // 4 consecutive output features
    int n0   = (tid >> 4) * 8;    // 8 nodes (4 pairs)

    const float* h = hFromH1 ? g_h1 : x;
    const bool hIsX = (hFromH1 == 0);

    ull accA[4][4], accS[4][4];   // [dd][pair]
#pragma unroll
    for (int dd = 0; dd < 4; dd++)
#pragma unroll
        for (int p = 0; p < 4; p++) { accA[dd][p] = 0ULL; accS[dd][p] = 0ULL; }

#pragma unroll
    for (int phase = 0; phase < 3; phase++) {
        const float* wsrc = (phase == 0) ? w_l : (phase == 1) ? w_r : w_skip;
        bool reuseAct = (phase == 2) && hIsX;    // layer 0: x already staged

        __syncthreads();
        // stage weights transposed: w[dd][kk] -> s_w[kk*WP + dd]
        for (int i = tid; i < 64 * 64; i += 256) {
            int dd = i >> 6, kk = i & 63;
            s_w[kk * WP + dd] = wsrc[i];
        }
        if (!reuseAct) {
            const float* am = (phase == 0) ? g_agg : (phase == 1) ? h : x;
            // k fast-varying with tid -> gmem coalesced; STS 2-way max
            for (int i = tid; i < DN * 64; i += 256) {
                int k = i & 63, n = i >> 6;
                int gn = base + n;
                s_act[k * AP + n] = (gn < N) ? am[gn * FEAT + k] : 0.f;
            }
        }
        __syncthreads();

        ull (*acc)[4] = (phase == 2) ? accS : accA;
#pragma unroll 2
        for (int k = 0; k < 64; k++) {
            float2 w01 = *(const float2*)&s_w[k * WP + d0];
            float2 w23 = *(const float2*)&s_w[k * WP + d0 + 2];
            ull wd[4];
            wd[0] = dup2(w01.x); wd[1] = dup2(w01.y);
            wd[2] = dup2(w23.x); wd[3] = dup2(w23.y);
            ull av[4];
#pragma unroll
            for (int p = 0; p < 4; p++)
                av[p] = *(const ull*)&s_act[k * AP + n0 + 2 * p];
#pragma unroll
            for (int dd = 0; dd < 4; dd++)
#pragma unroll
                for (int p = 0; p < 4; p++)
                    fma2(acc[dd][p], av[p], wd[dd]);
        }
    }

    // epilogue
    float bl[4], bs[4], ap[4];
#pragma unroll
    for (int dd = 0; dd < 4; dd++) {
        bl[dd] = b_l[d0 + dd];
        bs[dd] = b_skip[d0 + dd];
        ap[dd] = a[d0 + dd];
    }
    float fA[4][8], fS[4][8];
#pragma unroll
    for (int dd = 0; dd < 4; dd++)
#pragma unroll
        for (int p = 0; p < 4; p++) {
            unpk(fA[dd][2 * p], fA[dd][2 * p + 1], accA[dd][p]);
            unpk(fS[dd][2 * p], fS[dd][2 * p + 1], accS[dd][p]);
        }

    float* dstp = outToH1 ? g_h1 : out;
#pragma unroll
    for (int j = 0; j < 8; j++) {
        int gn = base + n0 + j;
        if (gn < N) {
            float4 v;
            float o;
            o = fA[0][j] + bl[0]; o = (o >= 0.f) ? o : ap[0] * o; v.x = o + fS[0][j] + bs[0];
            o = fA[1][j] + bl[1]; o = (o >= 0.f) ? o : ap[1] * o; v.y = o + fS[1][j] + bs[1];
            o = fA[2][j] + bl[2]; o = (o >= 0.f) ? o : ap[2] * o; v.z = o + fS[2][j] + bs[2];
            o = fA[3][j] + bl[3]; o = (o >= 0.f) ? o : ap[3] * o; v.w = o + fS[3][j] + bs[3];
            *(float4*)&dstp[gn * FEAT + d0] = v;
        }
    }
}

// ---------------------------------------------------------------------------
// Cleanup: restore call-entry invariants (g_cnt=0, g_bar=0).
// ---------------------------------------------------------------------------
__global__ void cleanup_kernel(int N)
{
    int i = blockIdx.x * blockDim.x + threadIdx.x;
    if (i < N) g_cnt[i] = 0;
    if (i == 0) g_bar = 0;
}

// ---------------------------------------------------------------------------
// Launch sequence (dense at index 3 -> ncu profiled slot).
// ---------------------------------------------------------------------------
extern "C" void kernel_launch(void* const* d_in, const int* in_sizes, int n_in,
                              void* d_out, int out_size)
{
    const float* x  = (const float*)d_in[0];
    const int*   ei = (const int*)d_in[1];   // int32 (JAX x64 disabled)
    int N = in_sizes[0] / FEAT;
    int E = in_sizes[1] / 2;
    const int* src = ei;
    const int* dst = ei + E;

    const float* w_l0    = (const float*)d_in[2];
    const float* b_l0    = (const float*)d_in[3];
    const float* w_r0    = (const float*)d_in[4];
    const float* w_skip0 = (const float*)d_in[5];
    const float* b_skip0 = (const float*)d_in[6];
    const float* a0      = (const float*)d_in[7];
    const float* w_l1    = (const float*)d_in[8];
    const float* b_l1    = (const float*)d_in[9];
    const float* w_r1    = (const float*)d_in[10];
    const float* w_skip1 = (const float*)d_in[11];
    const float* b_skip1 = (const float*)d_in[12];
    const float* a1      = (const float*)d_in[13];
    float* out = (float*)d_out;

    size_t dsmem = (size_t)(64 * WP + 64 * AP) * sizeof(float); // 50,176 B
    cudaFuncSetAttribute(dense_kernel, cudaFuncAttributeMaxDynamicSharedMemorySize,
                         (int)dsmem);

    int eblocks = (E + 255) / 256;
    int nb      = (N + SCAN_CHUNK - 1) / SCAN_CHUNK;   // 49
    int ablocks = (N * 32 + 255) / 256;
    int dblocks = (N + DN - 1) / DN;
    int nblocks = (N + 255) / 256;

    hist_kernel<<<eblocks, 256>>>(dst, E);                           // 0
    csr_build_kernel<<<nb, 256>>>(src, dst, N, E, nb);               // 1

    agg_kernel<<<ablocks, 256>>>(x, N, 0);                           // 2
    dense_kernel<<<dblocks, 256, dsmem>>>(x, w_l0, b_l0, w_r0,       // 3 <- profiled
                                          w_skip0, b_skip0, a0,
                                          out, N, 0, 1);

    agg_kernel<<<ablocks, 256>>>(x, N, 1);                           // 4
    dense_kernel<<<dblocks, 256, dsmem>>>(x, w_l1, b_l1, w_r1,       // 5
                                          w_skip1, b_skip1, a1,
                                          out, N, 1, 0);

    cleanup_kernel<<<nblocks, 256>>>(N);                             // 6
}

// round 8
// speedup vs baseline: 2.5377x; 1.0293x over previous
#include <cuda_runtime.h>

// Problem constants (shapes fixed by the dataset)
#define MAXN 100000
#define MAXE 1600000
#define FEAT 64
#define DN 128            // nodes per dense block
#define AP 132            // act smem stride (x4 floats -> 16B-aligned LDS.128)
#define WP 68             // weight smem stride (x4 floats -> 16B-aligned LDS.128)
#define SCAN_CHUNK 2048
#define MAXBLK 64

typedef unsigned long long ull;

// Scratch (__device__ globals; allocation-free rule). Zero-init at load;
// cleanup_kernel restores call-entry invariants every call.
__device__ float g_h1[MAXN * FEAT];
__device__ float g_agg[MAXN * FEAT];
__device__ int   g_cnt[MAXN];
__device__ int   g_off[MAXN];
__device__ int   g_cur[MAXN];
__device__ int   g_csr_src[MAXE];
__device__ int   g_bsum[MAXBLK];
__device__ int   g_bar;

// ---- packed f32x2 helpers (Blackwell PTX) ----------------------------------
__device__ __forceinline__ void fma2(ull& acc, ull av, ull wv)
{
    asm("fma.rn.f32x2 %0, %1, %2, %0;" : "+l"(acc) : "l"(av), "l"(wv));
}
__device__ __forceinline__ ull dup2(float w)
{
    ull r; asm("mov.b64 %0, {%1, %1};" : "=l"(r) : "f"(w)); return r;
}
__device__ __forceinline__ void unpk(float& lo, float& hi, ull v)
{
    asm("mov.b64 {%0, %1}, %2;" : "=f"(lo), "=f"(hi) : "l"(v));
}
__device__ __forceinline__ ull pk2(float lo, float hi)
{
    ull r; asm("mov.b64 %0, {%1, %2};" : "=l"(r) : "f"(lo), "f"(hi)); return r;
}

// Software grid barrier (all 49 blocks co-resident on 148 SMs).
__device__ __forceinline__ void grid_bar(int target)
{
    __syncthreads();
    if (threadIdx.x == 0) {
        __threadfence();
        atomicAdd(&g_bar, 1);
        while (atomicAdd(&g_bar, 0) < target) { }
    }
    __syncthreads();
}

// ---------------------------------------------------------------------------
// Fused CSR build (49 blocks): grid-stride histogram -> bar -> local scan ->
// bar -> global offsets -> bar -> bucket edges by dst.
// ---------------------------------------------------------------------------
__global__ void csr_build_kernel(const int* __restrict__ src,
                                 const int* __restrict__ dst,
                                 int N, int E, int nb)
{
    __shared__ int s_sum[256];
    int t = threadIdx.x;
    int gstride = gridDim.x * blockDim.x;

    // phase A: histogram (g_cnt is 0 on entry)
    for (int e = blockIdx.x * blockDim.x + t; e < E; e += gstride)
        atomicAdd(&g_cnt[dst[e]], 1);

    grid_bar(nb);

    // phase B: local exclusive scan (8 items/thread)
    int base = blockIdx.x * SCAN_CHUNK + t * 8;
    int v[8], tot = 0;
#pragma unroll
    for (int j = 0; j < 8; j++) {
        int idx = base + j;
        v[j] = (idx < N) ? g_cnt[idx] : 0;
        tot += v[j];
    }
    s_sum[t] = tot;
    __syncthreads();
    for (int off = 1; off < 256; off <<= 1) {
        int xv = (t >= off) ? s_sum[t - off] : 0;
        __syncthreads();
        s_sum[t] += xv;
        __syncthreads();
    }
    if (t == 255) g_bsum[blockIdx.x] = s_sum[255];
    int run = s_sum[t] - tot;

    grid_bar(2 * nb);

    // phase C: global offsets
    int bpre = 0;
    for (int b = 0; b < (int)blockIdx.x; b++) bpre += g_bsum[b];
    run += bpre;
#pragma unroll
    for (int j = 0; j < 8; j++) {
        int idx = base + j;
        if (idx < N) { g_off[idx] = run; g_cur[idx] = run; }
        run += v[j];
    }

    grid_bar(3 * nb);

    // phase D: bucket edges by dst (order within bucket irrelevant for a sum)
    for (int e = blockIdx.x * blockDim.x + t; e < E; e += gstride) {
        int p = atomicAdd(&g_cur[dst[e]], 1);
        g_csr_src[p] = src[e];
    }
}

// ---------------------------------------------------------------------------
// Aggregate: one warp per node; lane covers feats (2l, 2l+1) as float2.
// Unroll 8 for MLP depth; write mean once. No fp atomics; gathers hit the
// L2-resident feature table.
// ---------------------------------------------------------------------------
__global__ void agg_kernel(const float* __restrict__ x, int N, int hFromH1)
{
    int node = (int)((blockIdx.x * blockDim.x + threadIdx.x) >> 5);
    int lane = threadIdx.x & 31;
    if (node >= N) return;
    const float2* h2 = (const float2*)(hFromH1 ? g_h1 : x);

    int start = g_off[node];
    int deg   = g_cnt[node];

    float ax = 0.f, ay = 0.f;
    int i = 0;
    for (; i + 8 <= deg; i += 8) {
        int s[8];
#pragma unroll
        for (int j = 0; j < 8; j++) s[j] = g_csr_src[start + i + j];
        float2 v[8];
#pragma unroll
        for (int j = 0; j < 8; j++) v[j] = h2[s[j] * 32 + lane];
        float sx = ((v[0].x + v[1].x) + (v[2].x + v[3].x))
                 + ((v[4].x + v[5].x) + (v[6].x + v[7].x));
        float sy = ((v[0].y + v[1].y) + (v[2].y + v[3].y))
                 + ((v[4].y + v[5].y) + (v[6].y + v[7].y));
        ax += sx; ay += sy;
    }
    for (; i < deg; i++) {
        int s = g_csr_src[start + i];
        float2 v = h2[s * 32 + lane];
        ax += v.x; ay += v.y;
    }
    float inv = 1.f / fmaxf((float)deg, 1.f);
    float2 r; r.x = ax * inv; r.y = ay * inv;
    ((float2*)g_agg)[node * 32 + lane] = r;
}

// ---------------------------------------------------------------------------
// Dense phase, fused per node n:
//   o = PReLU( agg[n]@wl^T + bl + h[n]@wr^T ) + x0[n]@ws^T + bs
// Block: 256 threads, 64 feats x 128 nodes; thread tile 4d x 8n (4 f32x2
// pairs). ONE packed accumulator set: phases 0,1 accumulate; bias+PReLU
// applied in registers; phase 2 (skip) accumulates on top. Saves 32 regs ->
// 3 blocks/SM. Per k: 1 LDS.128 (w) + 2 LDS.128 (acts) + 4 dups + 16 FFMA2.
// Layer 0 reuses the x act-tile between phases 1 and 2.
// ---------------------------------------------------------------------------
__global__ void __launch_bounds__(256, 3) dense_kernel(
    const float* __restrict__ x,
    const float* __restrict__ w_l, const float* __restrict__ b_l,
    const float* __restrict__ w_r, const float* __restrict__ w_skip,
    const float* __restrict__ b_skip, const float* __restrict__ a,
    float* __restrict__ out, int N, int hFromH1, int outToH1)
{
    extern __shared__ __align__(16) float sm[];
    float* s_w   = sm;            // [64][WP]
    float* s_act = sm + 64 * WP;  // [64][AP]

    int tid  = threadIdx.x;
    int base = blockIdx.x * DN;
    int d0   = (tid & 15) * 4;    // 4 consecutive output features (16B-aligned)
    int n0   = (tid >> 4) * 8;    // 8 nodes (4 f32x2 pairs)

    const float* h = hFromH1 ? g_h1 : x;
    const bool hIsX = (hFromH1 == 0);

    // biases / slope (L2-resident broadcasts)
    float bl[4], bs[4], apar[4];
#pragma unroll
    for (int dd = 0; dd < 4; dd++) {
        bl[dd]   = b_l[d0 + dd];
        bs[dd]   = b_skip[d0 + dd];
        apar[dd] = a[d0 + dd];
    }

    ull acc[4][4];                // [dd][pair]
#pragma unroll
    for (int dd = 0; dd < 4; dd++)
#pragma unroll
        for (int p = 0; p < 4; p++) acc[dd][p] = 0ULL;

#pragma unroll
    for (int phase = 0; phase < 3; phase++) {
        const float* wsrc = (phase == 0) ? w_l : (phase == 1) ? w_r : w_skip;
        bool reuseAct = (phase == 2) && hIsX;   // layer 0: x already staged

        __syncthreads();
        // stage weights transposed: w[dd][kk] -> s_w[kk*WP + dd]
        for (int i = tid; i < 64 * 64; i += 256) {
            int dd = i >> 6, kk = i & 63;
            s_w[kk * WP + dd] = wsrc[i];
        }
        if (!reuseAct) {
            const float* am = (phase == 0) ? g_agg : (phase == 1) ? h : x;
            for (int i = tid; i < DN * 64; i += 256) {
                int k = i & 63, n = i >> 6;           // k fast -> gmem coalesced
                int gn = base + n;
                s_act[k * AP + n] = (gn < N) ? am[gn * FEAT + k] : 0.f;
            }
        }
        __syncthreads();

#pragma unroll 4
        for (int k = 0; k < 64; k++) {
            float4 w4 = *(const float4*)&s_w[k * WP + d0];
            ull wd[4];
            wd[0] = dup2(w4.x); wd[1] = dup2(w4.y);
            wd[2] = dup2(w4.z); wd[3] = dup2(w4.w);
            longlong2 p01 = *(const longlong2*)&s_act[k * AP + n0];
            longlong2 p23 = *(const longlong2*)&s_act[k * AP + n0 + 4];
            ull av[4];
            av[0] = (ull)p01.x; av[1] = (ull)p01.y;
            av[2] = (ull)p23.x; av[3] = (ull)p23.y;
#pragma unroll
            for (int dd = 0; dd < 4; dd++)
#pragma unroll
                for (int p = 0; p < 4; p++)
                    fma2(acc[dd][p], av[p], wd[dd]);
        }

        if (phase == 1) {
            // mid-epilogue in registers: acc = PReLU(acc + bl)
#pragma unroll
            for (int dd = 0; dd < 4; dd++)
#pragma unroll
                for (int p = 0; p < 4; p++) {
                    float lo, hi;
                    unpk(lo, hi, acc[dd][p]);
                    lo += bl[dd]; hi += bl[dd];
                    lo = (lo >= 0.f) ? lo : apar[dd] * lo;
                    hi = (hi >= 0.f) ? hi : apar[dd] * hi;
                    acc[dd][p] = pk2(lo, hi);
                }
        }
    }

    // final epilogue: out = acc + bs
    float* dstp = outToH1 ? g_h1 : out;
    float f[4][8];
#pragma unroll
    for (int dd = 0; dd < 4; dd++)
#pragma unroll
        for (int p = 0; p < 4; p++)
            unpk(f[dd][2 * p], f[dd][2 * p + 1], acc[dd][p]);
#pragma unroll
    for (int j = 0; j < 8; j++) {
        int gn = base + n0 + j;
        if (gn < N) {
            float4 v;
            v.x = f[0][j] + bs[0];
            v.y = f[1][j] + bs[1];
            v.z = f[2][j] + bs[2];
            v.w = f[3][j] + bs[3];
            *(float4*)&dstp[gn * FEAT + d0] = v;
        }
    }
}

// ---------------------------------------------------------------------------
// Cleanup: restore call-entry invariants (g_cnt=0, g_bar=0).
// ---------------------------------------------------------------------------
__global__ void cleanup_kernel(int N)
{
    int i = blockIdx.x * blockDim.x + threadIdx.x;
    if (i < N) g_cnt[i] = 0;
    if (i == 0) g_bar = 0;
}

// ---------------------------------------------------------------------------
// Launch sequence. Index 3 (ncu profiled slot) = layer-1 agg_kernel.
// ---------------------------------------------------------------------------
extern "C" void kernel_launch(void* const* d_in, const int* in_sizes, int n_in,
                              void* d_out, int out_size)
{
    const float* x  = (const float*)d_in[0];
    const int*   ei = (const int*)d_in[1];   // int32 (JAX x64 disabled)
    int N = in_sizes[0] / FEAT;
    int E = in_sizes[1] / 2;
    const int* src = ei;
    const int* dst = ei + E;

    const float* w_l0    = (const float*)d_in[2];
    const float* b_l0    = (const float*)d_in[3];
    const float* w_r0    = (const float*)d_in[4];
    const float* w_skip0 = (const float*)d_in[5];
    const float* b_skip0 = (const float*)d_in[6];
    const float* a0      = (const float*)d_in[7];
    const float* w_l1    = (const float*)d_in[8];
    const float* b_l1    = (const float*)d_in[9];
    const float* w_r1    = (const float*)d_in[10];
    const float* w_skip1 = (const float*)d_in[11];
    const float* b_skip1 = (const float*)d_in[12];
    const float* a1      = (const float*)d_in[13];
    float* out = (float*)d_out;

    size_t dsmem = (size_t)(64 * WP + 64 * AP) * sizeof(float); // 51,200 B
    cudaFuncSetAttribute(dense_kernel, cudaFuncAttributeMaxDynamicSharedMemorySize,
                         (int)dsmem);

    int nb      = (N + SCAN_CHUNK - 1) / SCAN_CHUNK;   // 49
    int ablocks = (N * 32 + 255) / 256;
    int dblocks = (N + DN - 1) / DN;
    int nblocks = (N + 255) / 256;

    csr_build_kernel<<<nb, 256>>>(src, dst, N, E, nb);               // 0

    agg_kernel<<<ablocks, 256>>>(x, N, 0);                           // 1
    dense_kernel<<<dblocks, 256, dsmem>>>(x, w_l0, b_l0, w_r0,       // 2
                                          w_skip0, b_skip0, a0,
                                          out, N, 0, 1);

    agg_kernel<<<ablocks, 256>>>(x, N, 1);                           // 3 <- profiled
    dense_kernel<<<dblocks, 256, dsmem>>>(x, w_l1, b_l1, w_r1,       // 4
                                          w_skip1, b_skip1, a1,
                                          out, N, 1, 0);

    cleanup_kernel<<<nblocks, 256>>>(N);                             // 5
}